// round 17
// baseline (speedup 1.0000x reference)
#include <cuda_runtime.h>
#include <cuda_fp16.h>
#include <cstdint>
#include <cstddef>

namespace {
constexpr int Bn = 32, Tn = 1024, INn = 1536, Dn = 768;
constexpr int Mn = Bn * Tn;  // 32768
constexpr int GSMEM = 72 * 1024;  // 3 stages x (A 16KB + B 8KB), fp16 K-tile 64
}

// Scratch (static __device__ globals: allocation-free rule)
__device__ __align__(256) __half g_Xh[(size_t)Mn * INn];
__device__ __align__(256) __half g_Hh[(size_t)Mn * INn];
__device__ __align__(256) float  g_U [(size_t)Mn * Dn];
__device__ __align__(256) __half g_Uh[(size_t)Mn * Dn];
__device__ __align__(256) float  g_XE[(size_t)Mn * Dn];
__device__ __align__(256) float  g_YE[(size_t)Mn * Dn];
__device__ __align__(256) __half g_W1[(size_t)INn * INn];
__device__ __align__(256) __half g_W2[(size_t)Dn * INn];
__device__ __align__(256) __half g_Wc[(size_t)3 * Dn * Dn];
__device__ __align__(256) float  g_PT[(size_t)36 * Mn];
__device__ __align__(256) float  g_PTY[(size_t)Bn * 8 * Dn];
__device__ __align__(256) float  g_PTF[(size_t)Bn * 8 * Dn];
__device__ __align__(256) float  g_WS[Mn];
__device__ __align__(256) float  g_YB[Bn * Dn];
__device__ __align__(256) float  g_UP[Mn];
__device__ __align__(256) float  g_INX[Mn];
__device__ __align__(256) float  g_INY[Mn];
__device__ __align__(256) float  g_SC[Mn];

// ---------------------------------------------------------------------------
// helpers
// ---------------------------------------------------------------------------
__device__ __forceinline__ uint32_t smem_u32(const void* p) {
    uint32_t a;
    asm("{ .reg .u64 t; cvta.to.shared.u64 t, %1; cvt.u32.u64 %0, t; }" : "=r"(a) : "l"(p));
    return a;
}
__device__ __forceinline__ void cp16(void* s, const void* g) {
    uint32_t sa = (uint32_t)__cvta_generic_to_shared(s);
    asm volatile("cp.async.cg.shared.global [%0], [%1], 16;\n" :: "r"(sa), "l"(g));
}
__device__ __forceinline__ void cp_commit() { asm volatile("cp.async.commit_group;\n"); }
template <int NW> __device__ __forceinline__ void cp_wait() {
    asm volatile("cp.async.wait_group %0;\n" :: "n"(NW));
}
// fp16 m16n8k16, fp32 accumulate
__device__ __forceinline__ void mma16(float* c, const uint32_t* a, const uint32_t* b) {
    asm volatile(
        "mma.sync.aligned.m16n8k16.row.col.f32.f16.f16.f32 "
        "{%0,%1,%2,%3}, {%4,%5,%6,%7}, {%8,%9}, {%0,%1,%2,%3};\n"
        : "+f"(c[0]), "+f"(c[1]), "+f"(c[2]), "+f"(c[3])
        : "r"(a[0]), "r"(a[1]), "r"(a[2]), "r"(a[3]), "r"(b[0]), "r"(b[1]));
}
__device__ __forceinline__ void ldsm4(uint32_t* r, uint32_t addr) {
    asm volatile("ldmatrix.sync.aligned.m8n8.x4.shared.b16 {%0,%1,%2,%3}, [%4];"
                 : "=r"(r[0]), "=r"(r[1]), "=r"(r[2]), "=r"(r[3]) : "r"(addr));
}
__device__ __forceinline__ void ldsm2(uint32_t* r, uint32_t addr) {
    asm volatile("ldmatrix.sync.aligned.m8n8.x2.shared.b16 {%0,%1}, [%2];"
                 : "=r"(r[0]), "=r"(r[1]) : "r"(addr));
}

// x -> fp16 (rn)
__global__ void cvt_x_k(const float4* __restrict__ src, __half* __restrict__ dst, int n4)
{
    int i = blockIdx.x * 256 + threadIdx.x;
    if (i >= n4) return;
    float4 v = src[i];
    __half2* d = (__half2*)(dst + (size_t)i * 4);
    d[0] = __floats2half2_rn(v.x, v.y);
    d[1] = __floats2half2_rn(v.z, v.w);
}
struct CvtBatch { const float4* s[5]; __half* d[5]; int off[6]; };
__global__ void cvt_batch_k(CvtBatch cb)
{
    int i = blockIdx.x * 256 + threadIdx.x;
    #pragma unroll
    for (int j = 0; j < 5; j++) {
        if (i >= cb.off[j] && i < cb.off[j + 1]) {
            int k = i - cb.off[j];
            float4 v = cb.s[j][k];
            __half2* d = (__half2*)(cb.d[j] + (size_t)k * 4);
            d[0] = __floats2half2_rn(v.x, v.y);
            d[1] = __floats2half2_rn(v.z, v.w);
        }
    }
}

// ---------------------------------------------------------------------------
// fp16 GEMM core: CTA 128(M)x64(N)x64(K), 128 threads, 4 warps 2x2, warp tile
// 64x32, m16n8k16 via ldmatrix (verified R14 addressing), 3-stage SINGLE-sync
// cp.async pipeline, 3 CTAs/SM.
// SMEM halves: A stage s at s*8192 (16KB), B stage s at 24576+s*4096 (8KB).
// Rows are 64 halves = 128 bytes. K%64==0, K/64>=2.
// ---------------------------------------------------------------------------
#define GEMM16_PRE_MAIN(APTR, WPTR, KVAL)                                               \
    extern __shared__ __half smh[];                                                     \
    const int tid  = threadIdx.x;                                                       \
    const int lane = tid & 31, wrp = tid >> 5;                                          \
    const int wm = wrp >> 1, wn = wrp & 1;                                              \
    const int m0 = blockIdx.y * 128, n0 = blockIdx.x * 64;                              \
    const int c4 = tid & 7, rb = tid >> 3;                                              \
    const int soff = rb * 64 + ((c4 ^ (rb & 7)) << 3);                                  \
    const __half* gA = (APTR) + (size_t)(m0 + rb) * (KVAL) + c4 * 8;                    \
    const __half* gW = (WPTR) + (size_t)(n0 + rb) * (KVAL) + c4 * 8;                    \
    auto load_stage = [&](int s, int k0) {                                              \
        __half* sA = smh + s * 8192;                                                    \
        __half* sB = smh + 24576 + s * 4096;                                            \
        _Pragma("unroll")                                                               \
        for (int p = 0; p < 8; p++) cp16(&sA[soff + p * 1024], gA + k0 + (size_t)p * 16 * (KVAL)); \
        _Pragma("unroll")                                                               \
        for (int p = 0; p < 4; p++) cp16(&sB[soff + p * 1024], gW + k0 + (size_t)p * 16 * (KVAL)); \
        cp_commit();                                                                    \
    };                                                                                  \
    const uint32_t smb = smem_u32(smh);                                                 \
    const int s7 = lane & 7;                                                            \
    const int half8 = (lane >> 3) & 1;                                                  \
    const int koffA = lane >> 4;                                                        \
    const int koffB = (lane >> 3) & 1;                                                  \
    uint32_t rowA[4], rowB[4];                                                          \
    _Pragma("unroll")                                                                   \
    for (int mf = 0; mf < 4; mf++)                                                      \
        rowA[mf] = (uint32_t)(wm * 64 + mf * 16 + half8 * 8 + s7) * 128u;               \
    _Pragma("unroll")                                                                   \
    for (int nf = 0; nf < 4; nf++)                                                      \
        rowB[nf] = (uint32_t)(wn * 32 + nf * 8 + s7) * 128u;                            \
    float acc[4][4][4];                                                                 \
    _Pragma("unroll")                                                                   \
    for (int i = 0; i < 4; i++)                                                         \
        _Pragma("unroll")                                                               \
        for (int j = 0; j < 4; j++)                                                     \
            _Pragma("unroll")                                                           \
            for (int q = 0; q < 4; q++) acc[i][j][q] = 0.f;                             \
    const int kiters = (KVAL) >> 6;                                                     \
    load_stage(0, 0);                                                                   \
    load_stage(1, 64);                                                                  \
    for (int it = 0; it < kiters; ++it) {                                               \
        if (it == kiters - 1) cp_wait<0>(); else cp_wait<1>();                          \
        __syncthreads();                                                                \
        if (it + 2 < kiters) load_stage((it + 2) % 3, (it + 2) << 6);                   \
        const int st = it % 3;                                                          \
        const uint32_t stA = smb + (uint32_t)st * 16384u;                               \
        const uint32_t stB = smb + 49152u + (uint32_t)st * 8192u;                       \
        _Pragma("unroll")                                                               \
        for (int kk = 0; kk < 8; kk += 2) {                                             \
            const uint32_t colA = (uint32_t)(((kk + koffA) ^ s7) << 4);                 \
            const uint32_t colB = (uint32_t)(((kk + koffB) ^ s7) << 4);                 \
            uint32_t af[4][4], bf[4][2];                                                \
            _Pragma("unroll")                                                           \
            for (int mf = 0; mf < 4; mf++) ldsm4(af[mf], stA + rowA[mf] + colA);        \
            _Pragma("unroll")                                                           \
            for (int nf = 0; nf < 4; nf++) ldsm2(bf[nf], stB + rowB[nf] + colB);        \
            _Pragma("unroll")                                                           \
            for (int mf = 0; mf < 4; mf++)                                              \
                _Pragma("unroll")                                                       \
                for (int nf = 0; nf < 4; nf++)                                          \
                    mma16(acc[mf][nf], af[mf], bf[nf]);                                 \
        }                                                                               \
    }

// MODE 1: fp16 output only (fc1 -> H). MODE 2: dual fp32 + fp16 (fc2 -> U,Uh).
template <bool RELU, int MODE>
__global__ __launch_bounds__(128, 3) void gemm_fp16(
    const __half* __restrict__ A, const __half* __restrict__ W,
    const float* __restrict__ bias, float* __restrict__ C,
    __half* __restrict__ Ch, int N, int K)
{
    GEMM16_PRE_MAIN(A, W, K)

    const int g = lane >> 2, t = lane & 3;
    #pragma unroll
    for (int mf = 0; mf < 4; mf++) {
        const int row = m0 + wm * 64 + mf * 16 + g;
        #pragma unroll
        for (int nf = 0; nf < 4; nf++) {
            const int col = n0 + wn * 32 + nf * 8 + 2 * t;
            const float b0 = bias[col], b1 = bias[col + 1];
            float v0 = acc[mf][nf][0] + b0;
            float v1 = acc[mf][nf][1] + b1;
            float v2 = acc[mf][nf][2] + b0;
            float v3 = acc[mf][nf][3] + b1;
            if (RELU) {
                v0 = fmaxf(v0, 0.f); v1 = fmaxf(v1, 0.f);
                v2 = fmaxf(v2, 0.f); v3 = fmaxf(v3, 0.f);
            }
            if (MODE == 2) {
                *(float2*)(C + (size_t)row       * N + col) = make_float2(v0, v1);
                *(float2*)(C + (size_t)(row + 8) * N + col) = make_float2(v2, v3);
            }
            *(__half2*)(Ch + (size_t)row       * N + col) = __floats2half2_rn(v0, v1);
            *(__half2*)(Ch + (size_t)(row + 8) * N + col) = __floats2half2_rn(v2, v3);
        }
    }
}

// Fused D-GEMM (fp16 operands): N=2304 concat [E | XE | YE]; 36 n-blocks.
__global__ __launch_bounds__(128, 3) void gemm_fused3(
    const __half* __restrict__ A, const __half* __restrict__ W,
    const float* __restrict__ b_e, const float* __restrict__ b_x,
    const float* __restrict__ b_y, const float* __restrict__ unred,
    float* __restrict__ XE, float* __restrict__ YE, float* __restrict__ PT)
{
    GEMM16_PRE_MAIN(A, W, 768)

    const int g = lane >> 2, t = lane & 3;
    const int seg = blockIdx.x / 12;             // 0:E 1:XE 2:YE
    const float* bias = (seg == 0) ? b_e : (seg == 1) ? b_x : b_y;
    float* Cseg = (seg == 1) ? XE : YE;
    const int cb0 = (blockIdx.x - seg * 12) * 64 + wn * 32;

    __syncthreads();               // single-sync mainloop: ensure stages dead
    float* part2 = (float*)smh;

    #pragma unroll
    for (int mf = 0; mf < 4; mf++) {
        const int row = wm * 64 + mf * 16 + g;
        float ps0 = 0.f, ps1 = 0.f;
        #pragma unroll
        for (int nf = 0; nf < 4; nf++) {
            const int cs = cb0 + nf * 8 + 2 * t;
            const float b0 = bias[cs], b1 = bias[cs + 1];
            float v0 = acc[mf][nf][0] + b0;
            float v1 = acc[mf][nf][1] + b1;
            float v2 = acc[mf][nf][2] + b0;
            float v3 = acc[mf][nf][3] + b1;
            if (seg == 0) {
                v0 = fmaxf(v0, 0.f); v1 = fmaxf(v1, 0.f);
                v2 = fmaxf(v2, 0.f); v3 = fmaxf(v3, 0.f);
                const float w0 = unred[cs], w1 = unred[cs + 1];
                ps0 += v0 * w0 + v1 * w1;
                ps1 += v2 * w0 + v3 * w1;
            } else {
                ps0 += v0 * v0 + v1 * v1;
                ps1 += v2 * v2 + v3 * v3;
                *(float2*)(Cseg + (size_t)(m0 + row)     * 768 + cs) = make_float2(v0, v1);
                *(float2*)(Cseg + (size_t)(m0 + row + 8) * 768 + cs) = make_float2(v2, v3);
            }
        }
        part2[row * 9 + wn * 4 + t]       = ps0;
        part2[(row + 8) * 9 + wn * 4 + t] = ps1;
    }
    __syncthreads();
    if (tid < 128) {
        float s = 0.f;
        #pragma unroll
        for (int c = 0; c < 8; c++) s += part2[tid * 9 + c];
        PT[(size_t)blockIdx.x * Mn + m0 + tid] = s;
    }
}

// --------------------------- tail kernels ----------------------------------
__global__ void combine_k(const float* __restrict__ PT, const float* __restrict__ unb,
                          float* __restrict__ up, float* __restrict__ inx,
                          float* __restrict__ iny)
{
    const int r = blockIdx.x * 256 + threadIdx.x;
    float a = 0.f, b = 0.f, c = 0.f;
    #pragma unroll
    for (int nb = 0; nb < 12; nb++)  a += PT[(size_t)nb * Mn + r];
    #pragma unroll
    for (int nb = 12; nb < 24; nb++) b += PT[(size_t)nb * Mn + r];
    #pragma unroll
    for (int nb = 24; nb < 36; nb++) c += PT[(size_t)nb * Mn + r];
    up[r]  = a + unb[0];
    inx[r] = 1.f / fmaxf(sqrtf(b), 1e-12f);
    iny[r] = 1.f / fmaxf(sqrtf(c), 1e-12f);
}

__global__ void ybar_part_k(const float* __restrict__ YE, const float* __restrict__ iny,
                            float* __restrict__ PTY)
{
    const int b = blockIdx.z, slice = blockIdx.y;
    const int col = blockIdx.x * 128 + threadIdx.x;
    const int t0 = slice * 128;
    const float* p = YE + ((size_t)b * 1024 + t0) * 768 + col;
    const float* w = iny + b * 1024 + t0;
    float s = 0.f;
    #pragma unroll 8
    for (int tt = 0; tt < 128; ++tt) s += p[(size_t)tt * 768] * w[tt];
    PTY[((size_t)(b * 8 + slice)) * 768 + col] = s;
}
__global__ void ybar_red_k(const float* __restrict__ PTY, float* __restrict__ YB)
{
    const int b = blockIdx.x, col = blockIdx.y * 128 + threadIdx.x;
    float s = 0.f;
    #pragma unroll
    for (int sl = 0; sl < 8; sl++) s += PTY[((size_t)(b * 8 + sl)) * 768 + col];
    YB[b * 768 + col] = s * (1.0f / 1024.0f);
}

__global__ void scores_k(const float* __restrict__ XE, const float* __restrict__ YB,
                         const float* __restrict__ invnx, const float* __restrict__ unpot,
                         const float* __restrict__ redw, float* __restrict__ sc)
{
    __shared__ float red[8];
    const int r = blockIdx.x, tid = threadIdx.x;
    const int b = r >> 10;
    const size_t base = (size_t)r * 768;
    const float* yb = YB + b * 768;
    float d = XE[base + tid] * yb[tid]
            + XE[base + tid + 256] * yb[tid + 256]
            + XE[base + tid + 512] * yb[tid + 512];
    #pragma unroll
    for (int o = 16; o; o >>= 1) d += __shfl_xor_sync(0xffffffffu, d, o);
    if ((tid & 31) == 0) red[tid >> 5] = d;
    __syncthreads();
    if (tid == 0) {
        float D = 0.f;
        #pragma unroll
        for (int i = 0; i < 8; i++) D += red[i];
        sc[r] = redw[0] * unpot[r] + redw[1] * (D * invnx[r]);
    }
}

__global__ void softmax_k(const float* __restrict__ sc, float* __restrict__ WS)
{
    __shared__ float red[8];
    __shared__ float finv;
    const int b = blockIdx.x, tid = threadIdx.x;
    float l0 = sc[b * 1024 + tid];
    float l1 = sc[b * 1024 + tid + 256];
    float l2 = sc[b * 1024 + tid + 512];
    float l3 = sc[b * 1024 + tid + 768];
    float mx = fmaxf(fmaxf(l0, l1), fmaxf(l2, l3));
    #pragma unroll
    for (int o = 16; o; o >>= 1) mx = fmaxf(mx, __shfl_xor_sync(0xffffffffu, mx, o));
    if ((tid & 31) == 0) red[tid >> 5] = mx;
    __syncthreads();
    if (tid == 0) {
        float M = red[0];
        #pragma unroll
        for (int i = 1; i < 8; i++) M = fmaxf(M, red[i]);
        finv = M;
    }
    __syncthreads();
    const float M = finv;
    __syncthreads();
    l0 = expf(l0 - M); l1 = expf(l1 - M); l2 = expf(l2 - M); l3 = expf(l3 - M);
    float s = l0 + l1 + l2 + l3;
    #pragma unroll
    for (int o = 16; o; o >>= 1) s += __shfl_xor_sync(0xffffffffu, s, o);
    if ((tid & 31) == 0) red[tid >> 5] = s;
    __syncthreads();
    if (tid == 0) {
        float S = 0.f;
        #pragma unroll
        for (int i = 0; i < 8; i++) S += red[i];
        finv = 1.f / S;
    }
    __syncthreads();
    const float inv = finv;
    WS[b * 1024 + tid]       = l0 * inv;
    WS[b * 1024 + tid + 256] = l1 * inv;
    WS[b * 1024 + tid + 512] = l2 * inv;
    WS[b * 1024 + tid + 768] = l3 * inv;
}

__global__ void wsum_k(const float* __restrict__ U, const float* __restrict__ WS,
                       float* __restrict__ PTF)
{
    __shared__ float wsh[128];
    const int slice = blockIdx.x, b = blockIdx.y, tid = threadIdx.x;
    const int t0 = slice * 128;
    if (tid < 128) wsh[tid] = WS[b * 1024 + t0 + tid];
    __syncthreads();
    const float* Ub = U + ((size_t)b * 1024 + t0) * 768;
    float a0 = 0.f, a1 = 0.f, a2 = 0.f;
    #pragma unroll 4
    for (int tt = 0; tt < 128; ++tt) {
        const float wt = wsh[tt];
        const float* row = Ub + (size_t)tt * 768;
        a0 += wt * row[tid];
        a1 += wt * row[tid + 256];
        a2 += wt * row[tid + 512];
    }
    float* pf = PTF + ((size_t)(b * 8 + slice)) * 768;
    pf[tid] = a0; pf[tid + 256] = a1; pf[tid + 512] = a2;
}
__global__ void wred_k(const float* __restrict__ PTF, float* __restrict__ out)
{
    const int b = blockIdx.x, tid = threadIdx.x;
    #pragma unroll
    for (int cblk = 0; cblk < 3; cblk++) {
        const int c = tid + cblk * 256;
        float s = 0.f;
        #pragma unroll
        for (int sl = 0; sl < 8; sl++) s += PTF[((size_t)(b * 8 + sl)) * 768 + c];
        out[b * 768 + c] = s;
    }
}

// ---------------------------------------------------------------------------
extern "C" void kernel_launch(void* const* d_in, const int* in_sizes, int n_in,
                              void* d_out, int out_size)
{
    (void)in_sizes; (void)n_in; (void)out_size;
    const float* x        = (const float*)d_in[0];
    const float* fc1_b    = (const float*)d_in[2];
    const float* fc2_b    = (const float*)d_in[4];
    const float* un_emb_b = (const float*)d_in[6];
    const float* un_red_w = (const float*)d_in[7];
    const float* un_red_b = (const float*)d_in[8];
    const float* pw_x_b   = (const float*)d_in[10];
    const float* pw_y_b   = (const float*)d_in[12];
    const float* red_w    = (const float*)d_in[13];
    float* out = (float*)d_out;

    __half *Xh, *Hh, *Uh, *W1, *W2, *Wc;
    float *U, *XE, *YE, *PT, *PTY, *PTF, *WS, *YB, *UP, *INX, *INY, *SC;
    cudaGetSymbolAddress((void**)&Xh,  g_Xh);
    cudaGetSymbolAddress((void**)&Hh,  g_Hh);
    cudaGetSymbolAddress((void**)&U,   g_U);
    cudaGetSymbolAddress((void**)&Uh,  g_Uh);
    cudaGetSymbolAddress((void**)&XE,  g_XE);
    cudaGetSymbolAddress((void**)&YE,  g_YE);
    cudaGetSymbolAddress((void**)&W1,  g_W1);
    cudaGetSymbolAddress((void**)&W2,  g_W2);
    cudaGetSymbolAddress((void**)&Wc,  g_Wc);
    cudaGetSymbolAddress((void**)&PT,  g_PT);
    cudaGetSymbolAddress((void**)&PTY, g_PTY);
    cudaGetSymbolAddress((void**)&PTF, g_PTF);
    cudaGetSymbolAddress((void**)&WS,  g_WS);
    cudaGetSymbolAddress((void**)&YB,  g_YB);
    cudaGetSymbolAddress((void**)&UP,  g_UP);
    cudaGetSymbolAddress((void**)&INX, g_INX);
    cudaGetSymbolAddress((void**)&INY, g_INY);
    cudaGetSymbolAddress((void**)&SC,  g_SC);

    cudaFuncSetAttribute((const void*)gemm_fp16<true, 1>,  cudaFuncAttributeMaxDynamicSharedMemorySize, GSMEM);
    cudaFuncSetAttribute((const void*)gemm_fp16<false, 2>, cudaFuncAttributeMaxDynamicSharedMemorySize, GSMEM);
    cudaFuncSetAttribute((const void*)gemm_fused3, cudaFuncAttributeMaxDynamicSharedMemorySize, GSMEM);

    // convert x + all weights to fp16 (rn)
    cvt_x_k<<<Mn * INn / 4 / 256, 256>>>((const float4*)x, Xh, Mn * INn / 4);
    {
        CvtBatch cb;
        const int n1 = INn * INn / 4, n2 = Dn * INn / 4, n3 = Dn * Dn / 4;
        cb.s[0] = (const float4*)d_in[1];  cb.d[0] = W1;
        cb.s[1] = (const float4*)d_in[3];  cb.d[1] = W2;
        cb.s[2] = (const float4*)d_in[5];  cb.d[2] = Wc;
        cb.s[3] = (const float4*)d_in[9];  cb.d[3] = Wc + (size_t)Dn * Dn;
        cb.s[4] = (const float4*)d_in[11]; cb.d[4] = Wc + (size_t)2 * Dn * Dn;
        cb.off[0] = 0; cb.off[1] = n1; cb.off[2] = n1 + n2;
        cb.off[3] = cb.off[2] + n3; cb.off[4] = cb.off[3] + n3; cb.off[5] = cb.off[4] + n3;
        cvt_batch_k<<<(cb.off[5] + 255) / 256, 256>>>(cb);
    }

    // 1. Hh = fp16(relu(Xh @ W1^T + b))   [32768 x 1536], K=1536
    gemm_fp16<true, 1><<<dim3(24, 256), 128, GSMEM>>>(Xh, W1, fc1_b, nullptr, Hh, 1536, 1536);
    // 2. U (fp32) + Uh (fp16) = Hh @ W2^T + b   [32768 x 768], K=1536
    gemm_fp16<false, 2><<<dim3(12, 256), 128, GSMEM>>>(Hh, W2, fc2_b, U, Uh, 768, 1536);
    // 3. fused E|XE|YE from Uh            [32768 x 2304], K=768; E never stored
    gemm_fused3<<<dim3(36, 256), 128, GSMEM>>>(Uh, Wc, un_emb_b, pw_x_b, pw_y_b,
                                               un_red_w, XE, YE, PT);
    // 4-9. combine, ybar (split), scores, softmax, weighted sum (split)
    combine_k<<<Mn / 256, 256>>>(PT, un_red_b, UP, INX, INY);
    ybar_part_k<<<dim3(6, 8, Bn), 128>>>(YE, INY, PTY);
    ybar_red_k<<<dim3(Bn, 6), 128>>>(PTY, YB);
    scores_k<<<Mn, 256>>>(XE, YB, INX, UP, red_w, SC);
    softmax_k<<<Bn, 256>>>(SC, WS);
    wsum_k<<<dim3(8, Bn), 256>>>(U, WS, PTF);
    wred_k<<<Bn, 256>>>(PTF, out);
}